// round 14
// baseline (speedup 1.0000x reference)
#include <cuda_runtime.h>
#include <cuda_pipeline.h>
#include <cstdint>

// Geometry fixed by setup_inputs: (16, 4, 1024, 1024) float32
#define BATCH 16
#define HH 1024
#define WW 1024
#define HW (HH * WW)

#define TILE_W 128
#define TILE_H 64
#define THREADS 512

// T1 region (phase-1 output): rows y0-1..y0+64 (66), cols x0-4..x0+131.
#define P1ROWS (TILE_H + 2)        // 66
#define QPR 34                     // T1 quads per row
#define SPITCH (QPR * 4)           // 136
#define NQUADS (P1ROWS * QPR)      // 2244

// Staged T region: rows clamp(y0-1+i), i=0..65; cols x0-8..x0+135.
#define TROWS 66
#define TQ 36                      // float4 quads per staged row
#define TPITCH (TQ * 4)            // 144
#define NSTAGE (TROWS * TQ)        // 2376 cp.asyncs

#define SMEM_BYTES ((TROWS * TPITCH + P1ROWS * SPITCH) * 4)  // 73920

#define RED_X 128
#define NPART (RED_X * BATCH)      // 2048 partials

__device__ float g_partials[NPART];

// ---------------------------------------------------------------------------
// Stage 1: per-block max(|u|,|v|) partials (unconditional writes, no reset).
// ---------------------------------------------------------------------------
__global__ __launch_bounds__(256)
void maxabs_kernel(const float* __restrict__ in) {
    const float4* __restrict__ base =
        reinterpret_cast<const float4*>(in + (size_t)blockIdx.y * 4 * HW);
    const int n4 = 2 * HW / 4;
    float m = 0.0f;
    #pragma unroll 8
    for (int i = blockIdx.x * 256 + threadIdx.x; i < n4; i += RED_X * 256) {
        float4 vv = base[i];
        m = fmaxf(m, fabsf(vv.x));
        m = fmaxf(m, fabsf(vv.y));
        m = fmaxf(m, fabsf(vv.z));
        m = fmaxf(m, fabsf(vv.w));
    }
    #pragma unroll
    for (int o = 16; o > 0; o >>= 1)
        m = fmaxf(m, __shfl_xor_sync(0xFFFFFFFFu, m, o));
    __shared__ float smax[8];
    int lane = threadIdx.x & 31, wid = threadIdx.x >> 5;
    if (lane == 0) smax[wid] = m;
    __syncthreads();
    if (threadIdx.x == 0) {
        float mm = smax[0];
        #pragma unroll
        for (int w = 1; w < 8; w++) mm = fmaxf(mm, smax[w]);
        g_partials[blockIdx.y * RED_X + blockIdx.x] = mm;
    }
}

// ---------------------------------------------------------------------------
// Stage 2 (fused): cp.async-stage T tile -> dt reduce (overlapped) ->
// advection from smem (3 LDS + 2 LDG per quad) -> row-factored 9-pt
// Laplacian (shuffle edges) + RaQ -> float4 out.
// ---------------------------------------------------------------------------
__global__ __launch_bounds__(THREADS, 3)
void fused_kernel(const float* __restrict__ in, float* __restrict__ out,
                  int out_size) {
    extern __shared__ float smem[];
    float* Tst = smem;                          // TROWS x TPITCH
    float* sT1 = smem + TROWS * TPITCH;         // P1ROWS x SPITCH
    __shared__ float swarp[THREADS / 32];
    __shared__ float s_dt;

    const int tid = threadIdx.x;
    const int x0 = blockIdx.x * TILE_W;
    const int y0 = blockIdx.y * TILE_H;
    const int b  = blockIdx.z;

    const float* __restrict__ U  = in + (size_t)b * 4 * HW;
    const float* __restrict__ V  = U + HW;
    const float* __restrict__ T  = U + 2 * HW;
    const float* __restrict__ Ra = U + 3 * HW;

    // ---- Kick off T staging first: zero-register async copies.
    //      Row i holds T[clamp(y0-1+i)], cols x0-8..x0+135 (x never clamped;
    //      out-of-range cols read adjacent channels and are never consumed).
    for (int s = tid; s < NSTAGE; s += THREADS) {
        int i = s / TQ;
        int j4 = (s - i * TQ) << 2;
        int rowc = min(max(y0 - 1 + i, 0), HH - 1);
        const float* src = T + (size_t)rowc * WW + (x0 - 8) + j4;
        __pipeline_memcpy_async(&Tst[i * TPITCH + j4], src, 16);
    }
    __pipeline_commit();

    // ---- dt prologue (overlaps with the async copy) ----
    {
        float m = 0.0f;
        #pragma unroll
        for (int i = 0; i < NPART / THREADS; i++)
            m = fmaxf(m, g_partials[tid + i * THREADS]);
        #pragma unroll
        for (int o = 16; o > 0; o >>= 1)
            m = fmaxf(m, __shfl_xor_sync(0xFFFFFFFFu, m, o));
        int lane = tid & 31, wid = tid >> 5;
        if (lane == 0) swarp[wid] = m;
        __syncthreads();
        if (tid == 0) {
            float mm = swarp[0];
            #pragma unroll
            for (int w = 1; w < THREADS / 32; w++) mm = fmaxf(mm, swarp[w]);
            const float dx = (float)(1.0 / 126.0);
            float dt_advect = 0.5f * 0.1f * dx / mm;
            float dx2 = dx * dx;
            float dt_diffuse = 0.5f * (dx2 * dx2) / (dx2 + dx2);
            s_dt = fminf(dt_advect, dt_diffuse);
        }
        __syncthreads();
    }
    const float dt = s_dt;

    const float dx = (float)(1.0 / 126.0);
    const float inv_dx = 1.0f / dx;

    // ---- Wait for staged T, make visible block-wide ----
    __pipeline_wait_prior(0);
    __syncthreads();

    // ---- Phase 1: advection. Interior tasks read T from smem. ----
    for (int q = tid; q < NQUADS; q += THREADS) {
        int ly = q / QPR;                   // 0..65
        int qi = q - ly * QPR;              // 0..33
        int gx0 = x0 - 4 + (qi << 2);

        float4 res;
        if (ly >= 1 && ly <= 64 && gx0 >= 1 && gx0 + 4 <= WW - 1) {
            // Interior: gy = y0-1+ly is in range; Tst row ly = T[gy],
            // row ly-1 = T[clamp(gy-1)], row ly+1 = T[clamp(gy+1)].
            int gy = y0 - 1 + ly;
            int row = gy * WW;
            const float* rc = &Tst[ly * TPITCH + (qi << 2)];
            const float4 c4 = *reinterpret_cast<const float4*>(rc + 4);
            float cl = rc[3];
            float cr = rc[8];
            const float4 t4 = *reinterpret_cast<const float4*>(rc + 4 - TPITCH);
            const float4 d4 = *reinterpret_cast<const float4*>(rc + 4 + TPITCH);
            const float4 u4 = *reinterpret_cast<const float4*>(U + row + gx0);
            const float4 v4 = *reinterpret_cast<const float4*>(V + row + gx0);

            float L[6] = {cl, c4.x, c4.y, c4.z, c4.w, cr};
            #pragma unroll
            for (int j = 0; j < 4; j++) {
                float c = L[j + 1];
                float u = (&u4.x)[j];
                float v = (&v4.x)[j];
                float t = (&t4.x)[j];
                float d = (&d4.x)[j];
                float dTdx = (u > 0.0f) ? (c - L[j]) * inv_dx
                                        : ((u < 0.0f) ? (L[j + 2] - c) * inv_dx : 0.0f);
                float dTdy = (v > 0.0f) ? (c - t) * inv_dx
                                        : ((v < 0.0f) ? (d - c) * inv_dx : 0.0f);
                (&res.x)[j] = c + dt * (-u * dTdx - v * dTdy);
            }
        } else {
            // y-halo rows and x-border quads: clamped global scalar path.
            int gy = min(max(y0 - 1 + ly, 0), HH - 1);
            int ym = max(gy - 1, 0), yp = min(gy + 1, HH - 1);
            int row = gy * WW;
            #pragma unroll
            for (int j = 0; j < 4; j++) {
                int gx = min(max(gx0 + j, 0), WW - 1);
                int xm = max(gx - 1, 0), xp = min(gx + 1, WW - 1);
                float c = T[row + gx];
                float l = T[row + xm];
                float r = T[row + xp];
                float t = T[ym * WW + gx];
                float d = T[yp * WW + gx];
                float u = U[row + gx];
                float v = V[row + gx];
                float dTdx = (u > 0.0f) ? (c - l) * inv_dx
                                        : ((u < 0.0f) ? (r - c) * inv_dx : 0.0f);
                float dTdy = (v > 0.0f) ? (c - t) * inv_dx
                                        : ((v < 0.0f) ? (d - c) * inv_dx : 0.0f);
                (&res.x)[j] = c + dt * (-u * dTdx - v * dTdy);
            }
        }
        *reinterpret_cast<float4*>(&sT1[ly * SPITCH + (qi << 2)]) = res;
    }
    __syncthreads();

    // ---- Phase 2: row-factored 9-pt Laplacian, vertical 4-row strips;
    //      edge floats via warp shuffle (R13 form). ----
    {
        const float dx2 = dx * dx;
        const float lap_scale = 0.25f / dx2;
        const int lane = tid & 31;
        const int cy = tid >> 5;          // 0..15
        const int qx = lane << 2;         // 0..124
        const int qy0 = cy << 2;          // 0..60

        float4 ra[4];
        #pragma unroll
        for (int r = 0; r < 4; r++)
            ra[r] = *reinterpret_cast<const float4*>(
                Ra + (size_t)(y0 + qy0 + r) * WW + (x0 + qx));

        float* outb = out + (size_t)b * HW;

        float h_m2[4], h_m1[4], c_m1[4];
        #pragma unroll
        for (int i = 0; i < 6; i++) {
            const float* srow = &sT1[(qy0 + i) * SPITCH];
            float4 m = *reinterpret_cast<const float4*>(srow + qx + 4);
            float le = __shfl_up_sync(0xFFFFFFFFu, m.w, 1);
            float re = __shfl_down_sync(0xFFFFFFFFu, m.x, 1);
            if (lane == 0)  le = srow[3];
            if (lane == 31) re = srow[132];

            float h[4];
            h[0] = le  + 2.0f * m.x + m.y;
            h[1] = m.x + 2.0f * m.y + m.z;
            h[2] = m.y + 2.0f * m.z + m.w;
            h[3] = m.z + 2.0f * m.w + re;

            if (i >= 2) {
                int oy = qy0 + i - 2;
                float4 res;
                #pragma unroll
                for (int jj = 0; jj < 4; jj++) {
                    float lap = h_m2[jj] + 2.0f * h_m1[jj] + h[jj]
                              - 16.0f * c_m1[jj];
                    (&res.x)[jj] = c_m1[jj]
                        + dt * (lap_scale * lap + (&ra[i - 2].x)[jj]);
                }
                *reinterpret_cast<float4*>(
                    outb + (size_t)(y0 + oy) * WW + (x0 + qx)) = res;
            }
            #pragma unroll
            for (int jj = 0; jj < 4; jj++) {
                h_m2[jj] = h_m1[jj];
                h_m1[jj] = h[jj];
            }
            c_m1[0] = m.x; c_m1[1] = m.y; c_m1[2] = m.z; c_m1[3] = m.w;
        }
    }

    if (tid == 0 && blockIdx.x == 0 && blockIdx.y == 0 && blockIdx.z == 0) {
        out[out_size - 1] = dt;
    }
}

extern "C" void kernel_launch(void* const* d_in, const int* in_sizes, int n_in,
                              void* d_out, int out_size) {
    const float* in = (const float*)d_in[0];
    float* out = (float*)d_out;

    static bool attr_set = false;
    if (!attr_set) {
        cudaFuncSetAttribute(fused_kernel,
                             cudaFuncAttributeMaxDynamicSharedMemorySize,
                             SMEM_BYTES);
        attr_set = true;
    }

    dim3 rgrid(RED_X, BATCH);
    maxabs_kernel<<<rgrid, 256>>>(in);

    dim3 fgrid(WW / TILE_W, HH / TILE_H, BATCH);  // 8 x 16 x 16 = 2048
    fused_kernel<<<fgrid, THREADS, SMEM_BYTES>>>(in, out, out_size);
}

// round 15
// speedup vs baseline: 1.0153x; 1.0153x over previous
#include <cuda_runtime.h>
#include <cstdint>
#include <climits>

// Geometry fixed by setup_inputs: (16, 4, 1024, 1024) float32
#define BATCH 16
#define HH 1024
#define WW 1024
#define HW (HH * WW)

#define SROWS 16                   // output rows per warp strip
#define WARPS 4
#define THREADS (WARPS * 32)       // 128
#define ROWS_PER_BLOCK (WARPS * SROWS)  // 64

#define RED_X 128
#define NPART (RED_X * BATCH)      // 2048 partials

__device__ float g_partials[NPART];

// ---------------------------------------------------------------------------
// Stage 1: per-block max(|u|,|v|) partials (unconditional writes, no reset).
// ---------------------------------------------------------------------------
__global__ __launch_bounds__(256)
void maxabs_kernel(const float* __restrict__ in) {
    const float4* __restrict__ base =
        reinterpret_cast<const float4*>(in + (size_t)blockIdx.y * 4 * HW);
    const int n4 = 2 * HW / 4;
    float m = 0.0f;
    #pragma unroll 8
    for (int i = blockIdx.x * 256 + threadIdx.x; i < n4; i += RED_X * 256) {
        float4 vv = base[i];
        m = fmaxf(m, fabsf(vv.x));
        m = fmaxf(m, fabsf(vv.y));
        m = fmaxf(m, fabsf(vv.z));
        m = fmaxf(m, fabsf(vv.w));
    }
    #pragma unroll
    for (int o = 16; o > 0; o >>= 1)
        m = fmaxf(m, __shfl_xor_sync(0xFFFFFFFFu, m, o));
    __shared__ float smax[8];
    int lane = threadIdx.x & 31, wid = threadIdx.x >> 5;
    if (lane == 0) smax[wid] = m;
    __syncthreads();
    if (threadIdx.x == 0) {
        float mm = smax[0];
        #pragma unroll
        for (int w = 1; w < 8; w++) mm = fmaxf(mm, smax[w]);
        g_partials[blockIdx.y * RED_X + blockIdx.x] = mm;
    }
}

__device__ __forceinline__ float upwind1(float c, float l, float r,
                                         float t, float d, float u, float v,
                                         float inv_dx, float dt) {
    float dTdx = (u > 0.0f) ? (c - l) * inv_dx
                            : ((u < 0.0f) ? (r - c) * inv_dx : 0.0f);
    float dTdy = (v > 0.0f) ? (c - t) * inv_dx
                            : ((v < 0.0f) ? (d - c) * inv_dx : 0.0f);
    return c + dt * (-u * dTdx - v * dTdy);
}

// ---------------------------------------------------------------------------
// Stage 2 (fused, one pass): dt reduce -> per-warp register-rolling strip:
// T1 (advection) computed on the fly, H-factored 9-pt Laplacian rolled in
// registers, output streamed. No smem tiles, no main-loop barriers.
// ---------------------------------------------------------------------------
__global__ __launch_bounds__(THREADS)
void fused_kernel(const float* __restrict__ in, float* __restrict__ out,
                  int out_size) {
    __shared__ float swarp[WARPS];
    __shared__ float s_dt;

    const int tid = threadIdx.x;
    const int lane = tid & 31;
    const int wid = tid >> 5;

    // ---- Prologue: reduce 2048 partials -> dt ----
    {
        float m = 0.0f;
        #pragma unroll
        for (int i = 0; i < NPART / THREADS; i++)
            m = fmaxf(m, g_partials[tid + i * THREADS]);
        #pragma unroll
        for (int o = 16; o > 0; o >>= 1)
            m = fmaxf(m, __shfl_xor_sync(0xFFFFFFFFu, m, o));
        if (lane == 0) swarp[wid] = m;
        __syncthreads();
        if (tid == 0) {
            float mm = swarp[0];
            #pragma unroll
            for (int w = 1; w < WARPS; w++) mm = fmaxf(mm, swarp[w]);
            const float dx = (float)(1.0 / 126.0);
            float dt_advect = 0.5f * 0.1f * dx / mm;
            float dx2 = dx * dx;
            float dt_diffuse = 0.5f * (dx2 * dx2) / (dx2 + dx2);
            s_dt = fminf(dt_advect, dt_diffuse);
        }
        __syncthreads();
    }
    const float dt = s_dt;

    const float dx = (float)(1.0 / 126.0);
    const float inv_dx = 1.0f / dx;
    const float dx2 = dx * dx;
    const float lap_scale = 0.25f / dx2;

    const int x0 = blockIdx.x * 128;
    const int wy0 = (blockIdx.y * WARPS + wid) * SROWS;
    const int b = blockIdx.z;
    const bool clampL = (x0 == 0);
    const bool clampR = (x0 + 128 == WW);

    const float* __restrict__ U  = in + (size_t)b * 4 * HW;
    const float* __restrict__ V  = U + HW;
    const float* __restrict__ T  = U + 2 * HW;
    const float* __restrict__ Ra = U + 3 * HW;
    float* __restrict__ outb = out + (size_t)b * HW;

    const int gxq = x0 + (lane << 2);   // this thread's quad base column

    // Rolling state
    float4 Tm, Tc, Tp;          // T rows clamp(rt-1), rt, clamp(rt+1)
    float4 c4;                  // T1 quad of current row rt
    float4 hq;                  // H(T1) of current row
    float4 h1, h2;              // H of previous two T1 rows
    float4 cprev;               // T1 quad of previous row
    int rt_prev = INT_MIN;

    for (int k = 0; k <= SROWS + 1; k++) {
        int r = wy0 - 1 + k;
        int rt = min(max(r, 0), HH - 1);

        if (rt != rt_prev) {
            int rtm = max(rt - 1, 0);
            int rtp = min(rt + 1, HH - 1);
            if (k == 0) {
                Tm = *reinterpret_cast<const float4*>(T + (size_t)rtm * WW + gxq);
                Tc = *reinterpret_cast<const float4*>(T + (size_t)rt  * WW + gxq);
            } else {
                Tm = Tc; Tc = Tp;
            }
            Tp = *reinterpret_cast<const float4*>(T + (size_t)rtp * WW + gxq);
            float4 u4 = *reinterpret_cast<const float4*>(U + (size_t)rt * WW + gxq);
            float4 v4 = *reinterpret_cast<const float4*>(V + (size_t)rt * WW + gxq);

            // Horizontal T neighbors of this row (shuffle; edges scalar/clamped).
            float cl = __shfl_up_sync(0xFFFFFFFFu, Tc.w, 1);
            float cr = __shfl_down_sync(0xFFFFFFFFu, Tc.x, 1);
            if (lane == 0)  cl = clampL ? Tc.x : T[(size_t)rt * WW + (x0 - 1)];
            if (lane == 31) cr = clampR ? Tc.w : T[(size_t)rt * WW + (x0 + 128)];

            float L[6] = {cl, Tc.x, Tc.y, Tc.z, Tc.w, cr};
            c4.x = upwind1(L[1], L[0], L[2], Tm.x, Tp.x, u4.x, v4.x, inv_dx, dt);
            c4.y = upwind1(L[2], L[1], L[3], Tm.y, Tp.y, u4.y, v4.y, inv_dx, dt);
            c4.z = upwind1(L[3], L[2], L[4], Tm.z, Tp.z, u4.z, v4.z, inv_dx, dt);
            c4.w = upwind1(L[4], L[3], L[5], Tm.w, Tp.w, u4.w, v4.w, inv_dx, dt);

            // Strip-edge T1 values (lanes 0 and 31 only).
            float t1e = 0.0f;
            if (lane == 0 && !clampL) {
                int ex = x0 - 1;
                size_t rowo = (size_t)rt * WW;
                float c = T[rowo + ex];
                float l = T[rowo + max(ex - 1, 0)];
                float t = T[(size_t)rtm * WW + ex];
                float d = T[(size_t)rtp * WW + ex];
                float uu = U[rowo + ex];
                float vv = V[rowo + ex];
                t1e = upwind1(c, l, Tc.x, t, d, uu, vv, inv_dx, dt);
            }
            if (lane == 31 && !clampR) {
                int ex = x0 + 128;
                size_t rowo = (size_t)rt * WW;
                float c = T[rowo + ex];
                float rr = T[rowo + min(ex + 1, WW - 1)];
                float t = T[(size_t)rtm * WW + ex];
                float d = T[(size_t)rtp * WW + ex];
                float uu = U[rowo + ex];
                float vv = V[rowo + ex];
                t1e = upwind1(c, Tc.w, rr, t, d, uu, vv, inv_dx, dt);
            }

            // Horizontal T1 neighbors -> H row.
            float le = __shfl_up_sync(0xFFFFFFFFu, c4.w, 1);
            float re = __shfl_down_sync(0xFFFFFFFFu, c4.x, 1);
            if (lane == 0)  le = clampL ? c4.x : t1e;
            if (lane == 31) re = clampR ? c4.w : t1e;

            hq.x = le   + 2.0f * c4.x + c4.y;
            hq.y = c4.x + 2.0f * c4.y + c4.z;
            hq.z = c4.y + 2.0f * c4.z + c4.w;
            hq.w = c4.z + 2.0f * c4.w + re;

            rt_prev = rt;
        }
        // else: clamped duplicate row — hq/c4 already hold the right values.

        if (k >= 2) {
            int oy = wy0 + k - 2;
            size_t gidx = (size_t)oy * WW + gxq;
            float4 ra = *reinterpret_cast<const float4*>(Ra + gidx);
            float4 res;
            res.x = cprev.x + dt * (lap_scale * (h2.x + 2.0f * h1.x + hq.x - 16.0f * cprev.x) + ra.x);
            res.y = cprev.y + dt * (lap_scale * (h2.y + 2.0f * h1.y + hq.y - 16.0f * cprev.y) + ra.y);
            res.z = cprev.z + dt * (lap_scale * (h2.z + 2.0f * h1.z + hq.z - 16.0f * cprev.z) + ra.z);
            res.w = cprev.w + dt * (lap_scale * (h2.w + 2.0f * h1.w + hq.w - 16.0f * cprev.w) + ra.w);
            *reinterpret_cast<float4*>(outb + gidx) = res;
        }

        h2 = h1;
        h1 = hq;
        cprev = c4;
    }

    if (tid == 0 && blockIdx.x == 0 && blockIdx.y == 0 && blockIdx.z == 0) {
        out[out_size - 1] = dt;
    }
}

extern "C" void kernel_launch(void* const* d_in, const int* in_sizes, int n_in,
                              void* d_out, int out_size) {
    const float* in = (const float*)d_in[0];
    float* out = (float*)d_out;

    dim3 rgrid(RED_X, BATCH);
    maxabs_kernel<<<rgrid, 256>>>(in);

    dim3 fgrid(WW / 128, HH / ROWS_PER_BLOCK, BATCH);  // 8 x 16 x 16 = 2048
    fused_kernel<<<fgrid, THREADS>>>(in, out, out_size);
}